// round 3
// baseline (speedup 1.0000x reference)
#include <cuda_runtime.h>
#include <cstdint>

// ---------------------------------------------------------------------------
// SpatioTemporalAttention on GB300 — Round 2 baseline
//
// Pipeline (all fp32):
//   1. Q = x_q  @ Wq + bq                     (GEMM 32768x1024x1024)
//   2. K = x_kv @ Wk + bk                     (GEMM)
//   3. V = x_kv @ Wv + bv                     (GEMM)
//   4. S = (Q @ Wqa + bqa)*scale              (logits, [32768,16])
//   5. pooled_q[n,c] = softmax_L(S) . Q       (softpool)
//   6. S = ((K*pooled_q) @ Wka + bka)*scale   (gated logits)
//   7. pooled_k[n,c] = softmax_L(S) . K       (softpool)
//   8. T = (V*pooled_k) @ Wt + bt             (GEMM, gate folded into A load,
//                                              written into K's buffer)
//   9. out = (T + Q) @ Wp + bp                (GEMM, residual folded into A load)
// ---------------------------------------------------------------------------

#define C_DIM 1024
#define H_DIM 16
#define DH_DIM 64
#define NB 8
#define LSEQ 4096
#define MTOT (NB * LSEQ)   // 32768

// Scratch (device globals — no allocations allowed)
__device__ float g_Q[(size_t)MTOT * C_DIM];   // queries (needed until step 9)
__device__ float g_K[(size_t)MTOT * C_DIM];   // keys, reused as T after step 7
__device__ float g_V[(size_t)MTOT * C_DIM];   // values
__device__ float g_S[(size_t)MTOT * H_DIM];   // attention logits
__device__ float g_pq[NB * C_DIM];            // pooled_q (grouped [N,C])
__device__ float g_pk[NB * C_DIM];            // pooled_k (grouped [N,C])

union F2U { unsigned long long u; float2 f; };

// ---------------------------------------------------------------------------
// SGEMM: C[M,N] = op(A)[M,K] @ B[K,N] + bias[N]
//   GATE: A element (row,k) multiplied by gate[(row/LSEQ)*C_DIM + k]
//   ADD : A element (row,k) gets addend[row*K + k] added
// BM=BN=128, BK=8, 256 threads, 8x8 per-thread microtile, f32x2 packed FMA.
// Requires M%128==0, N%128==0, K%8==0, LSEQ%128==0.
// ---------------------------------------------------------------------------
template <bool GATE, bool ADD>
__global__ __launch_bounds__(256, 2)
void sgemm_kernel(const float* __restrict__ A, const float* __restrict__ B,
                  const float* __restrict__ bias, float* __restrict__ Cc,
                  const float* __restrict__ gate, const float* __restrict__ addend,
                  int M, int N, int K)
{
    __shared__ float As[8][128];   // [k][m] (transposed)
    __shared__ float Bs[8][128];   // [k][n]

    const int tid  = threadIdx.x;
    const int m0   = blockIdx.y * 128;
    const int n0   = blockIdx.x * 128;
    const int trow = tid >> 4;           // 0..15
    const int tcol = tid & 15;           // 0..15
    const int arow = tid >> 1;           // 0..127
    const int acol = (tid & 1) * 4;      // 0 or 4
    const int brow = tid >> 5;           // 0..7
    const int bcol = (tid & 31) * 4;     // 0..124

    const float* gptr = nullptr;
    if (GATE) gptr = gate + (size_t)(m0 / LSEQ) * C_DIM;

    const float* Ag = A + (size_t)(m0 + arow) * K + acol;
    const float* Ad = nullptr;
    if (ADD) Ad = addend + (size_t)(m0 + arow) * K + acol;
    const float* Bg = B + (size_t)brow * N + n0 + bcol;

    unsigned long long acc[8][4];
    #pragma unroll
    for (int i = 0; i < 8; i++)
        #pragma unroll
        for (int j = 0; j < 4; j++) acc[i][j] = 0ull;

    for (int k0 = 0; k0 < K; k0 += 8) {
        float4 a4 = *(const float4*)(Ag + k0);
        if (ADD) {
            float4 d4 = *(const float4*)(Ad + k0);
            a4.x += d4.x; a4.y += d4.y; a4.z += d4.z; a4.w += d4.w;
        }
        if (GATE) {
            float4 g4 = *(const float4*)(gptr + k0 + acol);
            a4.x *= g4.x; a4.y *= g4.y; a4.z *= g4.z; a4.w *= g4.w;
        }
        As[acol + 0][arow] = a4.x;
        As[acol + 1][arow] = a4.y;
        As[acol + 2][arow] = a4.z;
        As[acol + 3][arow] = a4.w;

        *(float4*)&Bs[brow][bcol] = *(const float4*)(Bg + (size_t)k0 * N);
        __syncthreads();

        #pragma unroll
        for (int kk = 0; kk < 8; kk++) {
            float a_s[8];
            #pragma unroll
            for (int i = 0; i < 8; i++) a_s[i] = As[kk][trow * 8 + i];

            F2U bfr[4];
            const float2* bp2 = (const float2*)&Bs[kk][tcol * 8];
            #pragma unroll
            for (int j = 0; j < 4; j++) bfr[j].f = bp2[j];

            #pragma unroll
            for (int i = 0; i < 8; i++) {
                F2U ap; ap.f = make_float2(a_s[i], a_s[i]);
                #pragma unroll
                for (int j = 0; j < 4; j++) {
                    asm("fma.rn.f32x2 %0, %1, %2, %0;"
                        : "+l"(acc[i][j]) : "l"(ap.u), "l"(bfr[j].u));
                }
            }
        }
        __syncthreads();
    }

    float bias_r[8];
    #pragma unroll
    for (int j = 0; j < 8; j++) bias_r[j] = bias[n0 + tcol * 8 + j];

    #pragma unroll
    for (int i = 0; i < 8; i++) {
        float vals[8];
        #pragma unroll
        for (int j = 0; j < 4; j++) {
            F2U r; r.u = acc[i][j];
            vals[2 * j]     = r.f.x + bias_r[2 * j];
            vals[2 * j + 1] = r.f.y + bias_r[2 * j + 1];
        }
        float4* cp = (float4*)(Cc + (size_t)(m0 + trow * 8 + i) * N + n0 + tcol * 8);
        cp[0] = make_float4(vals[0], vals[1], vals[2], vals[3]);
        cp[1] = make_float4(vals[4], vals[5], vals[6], vals[7]);
    }
}

// ---------------------------------------------------------------------------
// Logits: S[row,h] = ((X[row,:] (* gate[batch,:])) @ W[:,16] + b[h]) * scale
// One warp per row; 8 warps/block; grid = MTOT/8 = 4096.
// ---------------------------------------------------------------------------
template <bool GATE>
__global__ __launch_bounds__(256)
void logits_kernel(const float* __restrict__ X, const float* __restrict__ W,
                   const float* __restrict__ b, const float* __restrict__ gate,
                   float* __restrict__ S)
{
    const int warp = threadIdx.x >> 5, lane = threadIdx.x & 31;
    const int row  = blockIdx.x * 8 + warp;
    const int bat  = row >> 12;   // row / 4096
    const float* xp = X + (size_t)row * C_DIM;
    const float* gp = GATE ? (gate + (size_t)bat * C_DIM) : nullptr;

    float acc[16];
    #pragma unroll
    for (int h = 0; h < 16; h++) acc[h] = 0.f;

    for (int c = lane; c < C_DIM; c += 32) {
        float a = xp[c];
        if (GATE) a *= gp[c];
        const float4* wp = (const float4*)(W + (size_t)c * 16);
        float4 w0 = wp[0], w1 = wp[1], w2 = wp[2], w3 = wp[3];
        acc[0]  += a * w0.x; acc[1]  += a * w0.y; acc[2]  += a * w0.z; acc[3]  += a * w0.w;
        acc[4]  += a * w1.x; acc[5]  += a * w1.y; acc[6]  += a * w1.z; acc[7]  += a * w1.w;
        acc[8]  += a * w2.x; acc[9]  += a * w2.y; acc[10] += a * w2.z; acc[11] += a * w2.w;
        acc[12] += a * w3.x; acc[13] += a * w3.y; acc[14] += a * w3.z; acc[15] += a * w3.w;
    }
    #pragma unroll
    for (int h = 0; h < 16; h++)
        #pragma unroll
        for (int off = 16; off; off >>= 1)
            acc[h] += __shfl_xor_sync(0xffffffffu, acc[h], off);

    if (lane == 0) {
        const float scale = 0.125f;   // 1/sqrt(DH)
        #pragma unroll
        for (int h = 0; h < 16; h++)
            S[(size_t)row * 16 + h] = (acc[h] + b[h]) * scale;
    }
}

// ---------------------------------------------------------------------------
// Softmax over L + weighted pooling.
// pooled[n, h*64+d] = sum_l softmax_l(S[n,l,h]) * X[n,l, h*64+d]
// grid = NB*H = 128, block = 256 (4 l-groups x 64 d-threads).
// ---------------------------------------------------------------------------
__global__ __launch_bounds__(256)
void softpool_kernel(const float* __restrict__ S, const float* __restrict__ X,
                     float* __restrict__ pooled)
{
    __shared__ float red[256];
    const int nh = blockIdx.x, n = nh >> 4, h = nh & 15;
    const int tid = threadIdx.x;
    const float* sp = S + (size_t)n * LSEQ * 16 + h;

    // pass 1: max over L
    float m = -1e30f;
    for (int l = tid; l < LSEQ; l += 256) m = fmaxf(m, sp[(size_t)l * 16]);
    red[tid] = m; __syncthreads();
    for (int s = 128; s; s >>= 1) { if (tid < s) red[tid] = fmaxf(red[tid], red[tid + s]); __syncthreads(); }
    m = red[0]; __syncthreads();

    // pass 2: sum of exp
    float sum = 0.f;
    for (int l = tid; l < LSEQ; l += 256) sum += __expf(sp[(size_t)l * 16] - m);
    red[tid] = sum; __syncthreads();
    for (int s = 128; s; s >>= 1) { if (tid < s) red[tid] += red[tid + s]; __syncthreads(); }
    const float invZ = 1.f / red[0]; __syncthreads();

    // pass 3: weighted pooling
    const int d = tid & 63, lg = tid >> 6;
    const float* xp = X + (size_t)n * LSEQ * C_DIM + h * 64 + d;
    float acc = 0.f;
    for (int l = lg; l < LSEQ; l += 4) {
        float w = __expf(sp[(size_t)l * 16] - m) * invZ;
        acc += w * xp[(size_t)l * C_DIM];
    }
    red[tid] = acc; __syncthreads();
    if (tid < 64)
        pooled[(size_t)n * C_DIM + h * 64 + d] =
            red[d] + red[64 + d] + red[128 + d] + red[192 + d];
}

// ---------------------------------------------------------------------------
extern "C" void kernel_launch(void* const* d_in, const int* in_sizes, int n_in,
                              void* d_out, int out_size)
{
    const float* x_q  = (const float*)d_in[0];
    const float* x_kv = (const float*)d_in[1];
    const float* Wq   = (const float*)d_in[2];
    const float* bq   = (const float*)d_in[3];
    const float* Wqa  = (const float*)d_in[4];
    const float* bqa  = (const float*)d_in[5];
    const float* Wk   = (const float*)d_in[6];
    const float* bk   = (const float*)d_in[7];
    const float* Wka  = (const float*)d_in[8];
    const float* bka  = (const float*)d_in[9];
    const float* Wv   = (const float*)d_in[10];
    const float* bv   = (const float*)d_in[11];
    const float* Wt   = (const float*)d_in[12];
    const float* bt   = (const float*)d_in[13];
    const float* Wp   = (const float*)d_in[14];
    const float* bp   = (const float*)d_in[15];
    float* out = (float*)d_out;

    float *Q, *K, *V, *S, *pq, *pk;
    cudaGetSymbolAddress((void**)&Q,  g_Q);
    cudaGetSymbolAddress((void**)&K,  g_K);
    cudaGetSymbolAddress((void**)&V,  g_V);
    cudaGetSymbolAddress((void**)&S,  g_S);
    cudaGetSymbolAddress((void**)&pq, g_pq);
    cudaGetSymbolAddress((void**)&pk, g_pk);

    dim3 gg(C_DIM / 128, MTOT / 128);   // (8, 256)

    // 1-3: projection GEMMs
    sgemm_kernel<false, false><<<gg, 256>>>(x_q,  Wq, bq, Q, nullptr, nullptr, MTOT, C_DIM, C_DIM);
    sgemm_kernel<false, false><<<gg, 256>>>(x_kv, Wk, bk, K, nullptr, nullptr, MTOT, C_DIM, C_DIM);
    sgemm_kernel<false, false><<<gg, 256>>>(x_kv, Wv, bv, V, nullptr, nullptr, MTOT, C_DIM, C_DIM);

    // 4-5: query softmax pooling
    logits_kernel<false><<<MTOT / 8, 256>>>(Q, Wqa, bqa, nullptr, S);
    softpool_kernel<<<NB * H_DIM, 256>>>(S, Q, pq);

    // 6-7: gated key softmax pooling
    logits_kernel<true><<<MTOT / 8, 256>>>(K, Wka, bka, pq, S);
    softpool_kernel<<<NB * H_DIM, 256>>>(S, K, pk);

    // 8: T = (V * pooled_k) @ Wt + bt   (into K's buffer)
    sgemm_kernel<true, false><<<gg, 256>>>(V, Wt, bt, K, pk, nullptr, MTOT, C_DIM, C_DIM);

    // 9: out = (T + Q) @ Wp + bp
    sgemm_kernel<false, true><<<gg, 256>>>(K, Wp, bp, out, nullptr, Q, MTOT, C_DIM, C_DIM);
}